// round 1
// baseline (speedup 1.0000x reference)
#include <cuda_runtime.h>
#include <cuda_bf16.h>

// Problem: B=8, SEQ=4096, DIM=64.
// out = scale * Q_r @ (K_r^T @ V_r)   (associativity; no softmax in reference)
// scale = 1/sqrt(64) = 0.125
//
// Inputs (metadata order): q, k, v, freq_q, freq_k, freq_v
//   q/k/v: (8, 4096, 64) fp32
//   freq_*: (4096, 32, 2) fp32 (cos, sin per pair)
// Output: (8, 4096, 64) fp32

#define BATCH   8
#define SEQ     4096
#define DIM     64
#define NCHUNK  32
#define CHUNK   (SEQ / NCHUNK)   // 128 rows per block in kernel 1

// Scratch (device globals — no allocation allowed in kernel_launch)
__device__ float g_partials[NCHUNK * BATCH * DIM * DIM];  // 4 MB
__device__ float g_M[BATCH * DIM * DIM];                  // 128 KB

// ---------------------------------------------------------------------------
// Kernel 1: per (chunk, batch) block compute partial M = sum_r k_r(row) ⊗ v_r(row)
// 256 threads: 16x16 thread tile, each owns a 4x4 sub-tile of the 64x64 M.
// ---------------------------------------------------------------------------
__global__ __launch_bounds__(256) void kv_outer_kernel(
    const float* __restrict__ K, const float* __restrict__ V,
    const float* __restrict__ FK, const float* __restrict__ FV)
{
    const int b = blockIdx.y;
    const int c = blockIdx.x;
    const int t = threadIdx.x;

    __shared__ float sk[8][DIM];
    __shared__ float sv[8][DIM];

    float acc[4][4];
#pragma unroll
    for (int i = 0; i < 4; i++)
#pragma unroll
        for (int j = 0; j < 4; j++) acc[i][j] = 0.0f;

    const int ti = t >> 4;        // 0..15
    const int tj = t & 15;        // 0..15
    const int i0 = ti * 4;
    const int j0 = tj * 4;

    const int lrow = t >> 5;      // 0..7  (row within 8-row tile)
    const int pair = t & 31;      // 0..31 (which (a,b) pair of the 64-dim row)

    const int row0 = c * CHUNK;
    const size_t base = ((size_t)b * SEQ) * DIM;

    for (int tile = 0; tile < CHUNK / 8; tile++) {
        const int row = row0 + tile * 8 + lrow;
        const float2 kp  = *(const float2*)&K [base + (size_t)row * DIM + 2 * pair];
        const float2 vp  = *(const float2*)&V [base + (size_t)row * DIM + 2 * pair];
        const float2 fkp = *(const float2*)&FK[(size_t)row * DIM + 2 * pair];
        const float2 fvp = *(const float2*)&FV[(size_t)row * DIM + 2 * pair];

        __syncthreads();   // previous tile's shared reads done
        sk[lrow][2 * pair]     = kp.x * fkp.x - kp.y * fkp.y;
        sk[lrow][2 * pair + 1] = kp.x * fkp.y + kp.y * fkp.x;
        sv[lrow][2 * pair]     = vp.x * fvp.x - vp.y * fvp.y;
        sv[lrow][2 * pair + 1] = vp.x * fvp.y + vp.y * fvp.x;
        __syncthreads();

#pragma unroll
        for (int r = 0; r < 8; r++) {
            const float4 kq = *(const float4*)&sk[r][i0];
            const float4 vq = *(const float4*)&sv[r][j0];
            const float kv_[4] = {kq.x, kq.y, kq.z, kq.w};
            const float vv_[4] = {vq.x, vq.y, vq.z, vq.w};
#pragma unroll
            for (int i = 0; i < 4; i++)
#pragma unroll
                for (int j = 0; j < 4; j++)
                    acc[i][j] = fmaf(kv_[i], vv_[j], acc[i][j]);
        }
    }

    float* P = &g_partials[((size_t)c * BATCH + b) * (DIM * DIM)];
#pragma unroll
    for (int i = 0; i < 4; i++) {
        float4 w = make_float4(acc[i][0], acc[i][1], acc[i][2], acc[i][3]);
        *(float4*)&P[(i0 + i) * DIM + j0] = w;
    }
}

// ---------------------------------------------------------------------------
// Kernel 2: reduce NCHUNK partials -> g_M  (BATCH*DIM*DIM = 32768 elements)
// ---------------------------------------------------------------------------
__global__ __launch_bounds__(256) void reduce_kernel()
{
    const int idx = blockIdx.x * 256 + threadIdx.x;   // 0..32767
    float s = 0.0f;
#pragma unroll
    for (int c = 0; c < NCHUNK; c++)
        s += g_partials[(size_t)c * (BATCH * DIM * DIM) + idx];
    g_M[idx] = s;
}

// ---------------------------------------------------------------------------
// Kernel 3: out[b,q,:] = scale * rope(Q[b,q,:]) @ M[b]
// 256 threads = 8 warps; each warp processes q rows, lane handles 2 output dims.
// ---------------------------------------------------------------------------
__global__ __launch_bounds__(256) void qm_kernel(
    const float* __restrict__ Q, const float* __restrict__ FQ,
    float* __restrict__ OUT)
{
    const int b = blockIdx.y;
    const int qchunk = blockIdx.x;          // 0..31, 128 rows each
    const int t = threadIdx.x;
    const int warp = t >> 5;
    const int lane = t & 31;

    __shared__ float sM[DIM][DIM];          // 16 KB
    __shared__ float sq[8][DIM];            // per-warp q row buffer

    // load M[b]
    {
        const float4* Msrc = (const float4*)&g_M[(size_t)b * DIM * DIM];
        float4* Mdst = (float4*)&sM[0][0];
#pragma unroll
        for (int i = 0; i < 4; i++)
            Mdst[t + i * 256] = Msrc[t + i * 256];
    }
    __syncthreads();

    const float scale = 0.125f;   // 1/sqrt(64)
    const size_t base = ((size_t)b * SEQ) * DIM;
    const int row0 = qchunk * 128;

    for (int it = 0; it < 16; it++) {
        const int row = row0 + it * 8 + warp;
        const float2 qp = *(const float2*)&Q [base + (size_t)row * DIM + 2 * lane];
        const float2 fq = *(const float2*)&FQ[(size_t)row * DIM + 2 * lane];

        sq[warp][2 * lane]     = qp.x * fq.x - qp.y * fq.y;
        sq[warp][2 * lane + 1] = qp.x * fq.y + qp.y * fq.x;
        __syncwarp();

        float acc0 = 0.0f, acc1 = 0.0f;
#pragma unroll
        for (int d = 0; d < DIM; d++) {
            const float qv = sq[warp][d];
            const float2 m = *(const float2*)&sM[d][2 * lane];
            acc0 = fmaf(qv, m.x, acc0);
            acc1 = fmaf(qv, m.y, acc1);
        }
        __syncwarp();   // before next iteration overwrites sq

        float2 o = make_float2(acc0 * scale, acc1 * scale);
        *(float2*)&OUT[base + (size_t)row * DIM + 2 * lane] = o;
    }
}

// ---------------------------------------------------------------------------
extern "C" void kernel_launch(void* const* d_in, const int* in_sizes, int n_in,
                              void* d_out, int out_size)
{
    const float* q  = (const float*)d_in[0];
    const float* k  = (const float*)d_in[1];
    const float* v  = (const float*)d_in[2];
    const float* fq = (const float*)d_in[3];
    const float* fk = (const float*)d_in[4];
    const float* fv = (const float*)d_in[5];
    float* out = (float*)d_out;

    kv_outer_kernel<<<dim3(NCHUNK, BATCH), 256>>>(k, v, fk, fv);
    reduce_kernel<<<(BATCH * DIM * DIM) / 256, 256>>>();
    qm_kernel<<<dim3(SEQ / 128, BATCH), 256>>>(q, fq, out);
}